// round 4
// baseline (speedup 1.0000x reference)
#include <cuda_runtime.h>

#define EDIM 1024
#define BB 2
#define SS 2048
#define HH 16
#define DD 64
#define NTOK (BB*SS)

// Scratch (allocation-free): Q,K,V in [B,H,S,D], attn output in [N,E]
__device__ float g_q[NTOK*EDIM];
__device__ float g_k[NTOK*EDIM];
__device__ float g_v[NTOK*EDIM];
__device__ float g_attn[NTOK*EDIM];

// ---------- tf32 helpers ----------
__device__ __forceinline__ unsigned f32_to_tf32(float x) {
    unsigned r;
    asm("cvt.rna.tf32.f32 %0, %1;" : "=r"(r) : "f"(x));
    return r;
}
__device__ __forceinline__ void split_tf32(float x, unsigned& hi, unsigned& lo) {
    hi = f32_to_tf32(x);
    lo = f32_to_tf32(x - __uint_as_float(hi));
}
__device__ __forceinline__ void mma_tf32(float c[4],
                                         const unsigned a[4],
                                         const unsigned b[2]) {
    asm volatile(
        "mma.sync.aligned.m16n8k8.row.col.f32.tf32.tf32.f32 "
        "{%0,%1,%2,%3}, {%4,%5,%6,%7}, {%8,%9}, {%0,%1,%2,%3};"
        : "+f"(c[0]), "+f"(c[1]), "+f"(c[2]), "+f"(c[3])
        : "r"(a[0]), "r"(a[1]), "r"(a[2]), "r"(a[3]), "r"(b[0]), "r"(b[1]));
}

// C[m,n] = (sum_k A[m,k]*W[n,k] + bias[n]) * scale   (A:[M,K] rowmajor, W:[N,K] rowmajor)
// 3xTF32 tensor-core GEMM (error-compensated: Ahi*Bhi + Ahi*Blo + Alo*Bhi ~ fp32 accuracy).
// CTA 128x128, 8 warps as 4(M)x2(N); warp tile 32x64 = 2x8 m16n8k8 tiles.
// smem [k][m]-major, pitch 132 -> conflict-free fragment LDS (banks (4q+g)%32 distinct).
// REMAP=true: write in [B,H,S,D] layout (m -> (b,s), n -> (h,d))
template<bool REMAP>
__global__ __launch_bounds__(256)
void gemm_nt_bias(const float* __restrict__ A, const float* __restrict__ W,
                  const float* __restrict__ bias, float* __restrict__ C,
                  float scale)
{
    const int K = EDIM;
    __shared__ float As[2][16][132];
    __shared__ float Ws[2][16][132];
    int tid = threadIdx.x;
    int bm = blockIdx.y * 128;
    int bn = blockIdx.x * 128;
    int lane = tid & 31, wid = tid >> 5;
    int warpM = (wid >> 1) * 32;       // 0,32,64,96
    int warpN = (wid & 1) * 64;        // 0,64
    int g = lane >> 2, q = lane & 3;   // fragment coords
    int lk4 = tid & 3, lm = tid >> 2;  // loader: 4 k-quads x 64 rows (x2 passes)

    float acc[2][8][4];
    #pragma unroll
    for (int mt = 0; mt < 2; mt++)
        #pragma unroll
        for (int nt = 0; nt < 8; nt++)
            #pragma unroll
            for (int i = 0; i < 4; i++) acc[mt][nt][i] = 0.f;

    float4 va[2], vb[2];

    // Prefetch k-tile 0 into registers
    #pragma unroll
    for (int p = 0; p < 2; p++) {
        int m = lm + p * 64;
        va[p] = *(const float4*)&A[(size_t)(bm + m) * K + lk4 * 4];
        vb[p] = *(const float4*)&W[(size_t)(bn + m) * K + lk4 * 4];
    }
    #pragma unroll
    for (int p = 0; p < 2; p++) {
        int m = lm + p * 64;
        As[0][lk4*4+0][m] = va[p].x; As[0][lk4*4+1][m] = va[p].y;
        As[0][lk4*4+2][m] = va[p].z; As[0][lk4*4+3][m] = va[p].w;
        Ws[0][lk4*4+0][m] = vb[p].x; Ws[0][lk4*4+1][m] = vb[p].y;
        Ws[0][lk4*4+2][m] = vb[p].z; Ws[0][lk4*4+3][m] = vb[p].w;
    }
    __syncthreads();

    int buf = 0;
    for (int k0 = 0; k0 < K; k0 += 16) {
        bool has_next = (k0 + 16) < K;
        if (has_next) {   // issue next tile's global loads; hidden by mma block
            #pragma unroll
            for (int p = 0; p < 2; p++) {
                int m = lm + p * 64;
                va[p] = *(const float4*)&A[(size_t)(bm + m) * K + k0 + 16 + lk4 * 4];
                vb[p] = *(const float4*)&W[(size_t)(bn + m) * K + k0 + 16 + lk4 * 4];
            }
        }
        // Two k8 mma steps over current buffer
        #pragma unroll
        for (int ks = 0; ks < 2; ks++) {
            int k8 = ks * 8;
            unsigned ah[2][4], al[2][4], bh[8][2], bl[8][2];
            #pragma unroll
            for (int mt = 0; mt < 2; mt++) {
                int row = warpM + mt * 16 + g;
                split_tf32(As[buf][k8 + q][row],       ah[mt][0], al[mt][0]);
                split_tf32(As[buf][k8 + q][row + 8],   ah[mt][1], al[mt][1]);
                split_tf32(As[buf][k8 + 4 + q][row],     ah[mt][2], al[mt][2]);
                split_tf32(As[buf][k8 + 4 + q][row + 8], ah[mt][3], al[mt][3]);
            }
            #pragma unroll
            for (int nt = 0; nt < 8; nt++) {
                int col = warpN + nt * 8 + g;
                split_tf32(Ws[buf][k8 + q][col],     bh[nt][0], bl[nt][0]);
                split_tf32(Ws[buf][k8 + 4 + q][col], bh[nt][1], bl[nt][1]);
            }
            #pragma unroll
            for (int mt = 0; mt < 2; mt++)
                #pragma unroll
                for (int nt = 0; nt < 8; nt++) {
                    mma_tf32(acc[mt][nt], ah[mt], bh[nt]);  // hi*hi
                    mma_tf32(acc[mt][nt], ah[mt], bl[nt]);  // hi*lo
                    mma_tf32(acc[mt][nt], al[mt], bh[nt]);  // lo*hi
                }
        }
        if (has_next) {
            int nb = buf ^ 1;
            #pragma unroll
            for (int p = 0; p < 2; p++) {
                int m = lm + p * 64;
                As[nb][lk4*4+0][m] = va[p].x; As[nb][lk4*4+1][m] = va[p].y;
                As[nb][lk4*4+2][m] = va[p].z; As[nb][lk4*4+3][m] = va[p].w;
                Ws[nb][lk4*4+0][m] = vb[p].x; Ws[nb][lk4*4+1][m] = vb[p].y;
                Ws[nb][lk4*4+2][m] = vb[p].z; Ws[nb][lk4*4+3][m] = vb[p].w;
            }
            __syncthreads();
            buf = nb;
        }
    }

    // Epilogue: c0,c1 = (row g,   cols 2q, 2q+1); c2,c3 = (row g+8, same cols)
    #pragma unroll
    for (int mt = 0; mt < 2; mt++) {
        int r0 = bm + warpM + mt * 16 + g;
        #pragma unroll
        for (int nt = 0; nt < 8; nt++) {
            int n = bn + warpN + nt * 8 + q * 2;
            float bia0 = bias[n], bia1 = bias[n + 1];
            float2 vlo = make_float2((acc[mt][nt][0] + bia0) * scale,
                                     (acc[mt][nt][1] + bia1) * scale);
            float2 vhi = make_float2((acc[mt][nt][2] + bia0) * scale,
                                     (acc[mt][nt][3] + bia1) * scale);
            if (REMAP) {
                int h = n >> 6, d = n & 63;
                int b0i = r0 >> 11, s0 = r0 & (SS - 1);
                int b1i = (r0 + 8) >> 11, s1 = (r0 + 8) & (SS - 1);
                *(float2*)&C[(((size_t)b0i * HH + h) * SS + s0) * DD + d] = vlo;
                *(float2*)&C[(((size_t)b1i * HH + h) * SS + s1) * DD + d] = vhi;
            } else {
                *(float2*)&C[(size_t)r0 * EDIM + n] = vlo;
                *(float2*)&C[(size_t)(r0 + 8) * EDIM + n] = vhi;
            }
        }
    }
}

// Flash attention: 64-query tile per CTA, loop over 64-key tiles.
// Register prefetch of next K/V tile hides gmem/L2 latency behind compute.
// smem (floats): Qt [64d][72] transposed, Kt/Ps [64][72] (reused), Vs [64][64]
#define SM_QT 0
#define SM_KT 4608
#define SM_VS 9216
#define FLASH_SMEM_BYTES 53248

__global__ __launch_bounds__(256)
void flash_attn(const float* __restrict__ Q, const float* __restrict__ K,
                const float* __restrict__ V, float* __restrict__ O)
{
    extern __shared__ float sm[];
    int tid = threadIdx.x;
    int tx = tid & 15, ty = tid >> 4;
    int qt = blockIdx.x, h = blockIdx.y, b = blockIdx.z;
    const size_t base = ((size_t)b * HH + h) * SS * DD;
    int q0 = qt * 64;

    // Load Q tile transposed: Qt[d][q]
    #pragma unroll
    for (int p = 0; p < 4; p++) {
        int r = ty + p * 16;
        float4 v = *(const float4*)&Q[base + (size_t)(q0 + r) * DD + tx * 4];
        sm[SM_QT + (tx*4+0)*72 + r] = v.x;
        sm[SM_QT + (tx*4+1)*72 + r] = v.y;
        sm[SM_QT + (tx*4+2)*72 + r] = v.z;
        sm[SM_QT + (tx*4+3)*72 + r] = v.w;
    }

    float o[4][4], mI[4], lI[4];
    #pragma unroll
    for (int i = 0; i < 4; i++) {
        mI[i] = -1e30f; lI[i] = 0.f;
        #pragma unroll
        for (int j = 0; j < 4; j++) o[i][j] = 0.f;
    }

    // Register prefetch of K/V tile 0
    float4 kpre[4], vpre[4];
    #pragma unroll
    for (int p = 0; p < 4; p++) {
        int r = ty + p * 16;
        kpre[p] = *(const float4*)&K[base + (size_t)r * DD + tx * 4];
        vpre[p] = *(const float4*)&V[base + (size_t)r * DD + tx * 4];
    }

    for (int kt = 0; kt < SS / 64; kt++) {
        __syncthreads();   // previous PV done before overwriting Kt/Vs
        #pragma unroll
        for (int p = 0; p < 4; p++) {
            int r = ty + p * 16;
            sm[SM_KT + (tx*4+0)*72 + r] = kpre[p].x;
            sm[SM_KT + (tx*4+1)*72 + r] = kpre[p].y;
            sm[SM_KT + (tx*4+2)*72 + r] = kpre[p].z;
            sm[SM_KT + (tx*4+3)*72 + r] = kpre[p].w;
            *(float4*)&sm[SM_VS + r * 64 + tx * 4] = vpre[p];
        }
        if (kt + 1 < SS / 64) {
            int k0n = (kt + 1) * 64;
            #pragma unroll
            for (int p = 0; p < 4; p++) {
                int r = ty + p * 16;
                kpre[p] = *(const float4*)&K[base + (size_t)(k0n + r) * DD + tx * 4];
                vpre[p] = *(const float4*)&V[base + (size_t)(k0n + r) * DD + tx * 4];
            }
        }
        __syncthreads();

        // S = Q K^T : thread owns q rows ty*4+i, key cols tx*4+j
        float s[4][4];
        #pragma unroll
        for (int i = 0; i < 4; i++)
            #pragma unroll
            for (int j = 0; j < 4; j++) s[i][j] = 0.f;
        #pragma unroll 4
        for (int kd = 0; kd < 64; kd++) {
            float4 qa = *(float4*)&sm[SM_QT + kd * 72 + ty * 4];
            float4 kb = *(float4*)&sm[SM_KT + kd * 72 + tx * 4];
            float a[4] = {qa.x, qa.y, qa.z, qa.w};
            float c[4] = {kb.x, kb.y, kb.z, kb.w};
            #pragma unroll
            for (int i = 0; i < 4; i++)
                #pragma unroll
                for (int j = 0; j < 4; j++) s[i][j] += a[i] * c[j];
        }

        // Online softmax (reduce across the 16-lane tx group; lane bits 0..3 = tx)
        float p[4][4];
        #pragma unroll
        for (int i = 0; i < 4; i++) {
            float mt = fmaxf(fmaxf(s[i][0], s[i][1]), fmaxf(s[i][2], s[i][3]));
            #pragma unroll
            for (int off = 8; off > 0; off >>= 1)
                mt = fmaxf(mt, __shfl_xor_sync(0xffffffffu, mt, off));
            float mNew = fmaxf(mI[i], mt);
            float corr = __expf(mI[i] - mNew);
            float rs = 0.f;
            #pragma unroll
            for (int j = 0; j < 4; j++) {
                p[i][j] = __expf(s[i][j] - mNew);
                rs += p[i][j];
            }
            #pragma unroll
            for (int off = 8; off > 0; off >>= 1)
                rs += __shfl_xor_sync(0xffffffffu, rs, off);
            lI[i] = lI[i] * corr + rs;
            mI[i] = mNew;
            #pragma unroll
            for (int j = 0; j < 4; j++) o[i][j] *= corr;
        }

        __syncthreads();   // everyone done reading Kt
        #pragma unroll
        for (int i = 0; i < 4; i++)
            *(float4*)&sm[SM_KT + (ty * 4 + i) * 72 + tx * 4] =
                make_float4(p[i][0], p[i][1], p[i][2], p[i][3]);
        __syncthreads();

        // O += P V : thread owns q rows ty*4+i, d cols tx*4+j
        #pragma unroll 4
        for (int k = 0; k < 64; k++) {
            float4 vv = *(float4*)&sm[SM_VS + k * 64 + tx * 4];
            #pragma unroll
            for (int i = 0; i < 4; i++) {
                float pv = sm[SM_KT + (ty * 4 + i) * 72 + k];
                o[i][0] += pv * vv.x; o[i][1] += pv * vv.y;
                o[i][2] += pv * vv.z; o[i][3] += pv * vv.w;
            }
        }
    }

    // Normalize and write to [N, E] layout for the output projection
    #pragma unroll
    for (int i = 0; i < 4; i++) {
        float inv = 1.f / lI[i];
        int n = b * SS + q0 + ty * 4 + i;
        float4 ov = make_float4(o[i][0]*inv, o[i][1]*inv, o[i][2]*inv, o[i][3]*inv);
        *(float4*)&O[(size_t)n * EDIM + h * 64 + tx * 4] = ov;
    }
}

extern "C" void kernel_launch(void* const* d_in, const int* in_sizes, int n_in,
                              void* d_out, int out_size) {
    const float* x  = (const float*)d_in[0];
    const float* Wq = (const float*)d_in[1];
    const float* bq = (const float*)d_in[2];
    const float* Wk = (const float*)d_in[3];
    const float* bk = (const float*)d_in[4];
    const float* Wv = (const float*)d_in[5];
    const float* bv = (const float*)d_in[6];
    const float* Wo = (const float*)d_in[7];
    const float* bo = (const float*)d_in[8];
    float* out = (float*)d_out;

    float *q, *k, *v, *attn;
    cudaGetSymbolAddress((void**)&q, g_q);
    cudaGetSymbolAddress((void**)&k, g_k);
    cudaGetSymbolAddress((void**)&v, g_v);
    cudaGetSymbolAddress((void**)&attn, g_attn);

    cudaFuncSetAttribute(flash_attn, cudaFuncAttributeMaxDynamicSharedMemorySize,
                         FLASH_SMEM_BYTES);

    dim3 gthr(256);
    dim3 ggrid(EDIM / 128, NTOK / 128);   // (8, 32)

    const float qscale = 0.125f;          // 1/sqrt(64)
    gemm_nt_bias<true><<<ggrid, gthr>>>(x, Wq, bq, q, qscale);
    gemm_nt_bias<true><<<ggrid, gthr>>>(x, Wk, bk, k, 1.f);
    gemm_nt_bias<true><<<ggrid, gthr>>>(x, Wv, bv, v, 1.f);

    flash_attn<<<dim3(SS / 64, HH, BB), 256, FLASH_SMEM_BYTES>>>(q, k, v, attn);

    gemm_nt_bias<false><<<ggrid, gthr>>>(attn, Wo, bo, out, 1.f);
}

// round 10
// speedup vs baseline: 1.4799x; 1.4799x over previous
#include <cuda_runtime.h>

#define EDIM 1024
#define BB 2
#define SS 2048
#define HH 16
#define DD 64
#define NTOK (BB*SS)

// Scratch (allocation-free): Q,K,V in [B,H,S,D], attn output in [N,E]
__device__ float g_q[NTOK*EDIM];
__device__ float g_k[NTOK*EDIM];
__device__ float g_v[NTOK*EDIM];
__device__ float g_attn[NTOK*EDIM];

// ---------- tf32 helpers ----------
// Exact split: hi keeps tf32's 10 explicit mantissa bits (truncation), lo = x - hi
// is exact in fp32. mma reads tf32 operands (low 13 mantissa bits ignored), so
// hi*bh + hi*bl + lo*bh reconstructs fp32-accuracy products (residual ~2^-43).
__device__ __forceinline__ void split2(float x, unsigned& hi, unsigned& lo) {
    hi = __float_as_uint(x) & 0xFFFFE000u;
    lo = __float_as_uint(x - __uint_as_float(hi));
}
__device__ __forceinline__ void mma_tf32(float c[4],
                                         const unsigned a[4],
                                         const unsigned b[2]) {
    asm volatile(
        "mma.sync.aligned.m16n8k8.row.col.f32.tf32.tf32.f32 "
        "{%0,%1,%2,%3}, {%4,%5,%6,%7}, {%8,%9}, {%0,%1,%2,%3};"
        : "+f"(c[0]), "+f"(c[1]), "+f"(c[2]), "+f"(c[3])
        : "r"(a[0]), "r"(a[1]), "r"(a[2]), "r"(a[3]), "r"(b[0]), "r"(b[1]));
}
__device__ __forceinline__ float ex2(float x) {
    float r;
    asm("ex2.approx.ftz.f32 %0, %1;" : "=f"(r) : "f"(x));
    return r;
}
__device__ __forceinline__ void cp_async16(unsigned saddr, const void* gptr) {
    asm volatile("cp.async.cg.shared.global [%0], [%1], 16;"
                 :: "r"(saddr), "l"(gptr));
}
#define CP_COMMIT() asm volatile("cp.async.commit_group;" ::: "memory")
#define CP_WAIT0()  asm volatile("cp.async.wait_group 0;" ::: "memory")

// Shared GEMM body: C[m,n] = (sum_k A[m,k]*W[n,k] + bias[n]) * scale
// 3xTF32 error-compensated; layout validated in R4 (rel_err 7.5e-6).
template<bool REMAP>
__device__ __forceinline__
void gemm_body(const float* __restrict__ A, const float* __restrict__ W,
               const float* __restrict__ bias, float* __restrict__ C,
               float scale,
               float (*As)[16][132], float (*Ws)[16][132],
               int bm, int bn)
{
    const int K = EDIM;
    int tid = threadIdx.x;
    int lane = tid & 31, wid = tid >> 5;
    int warpM = (wid >> 1) * 32;
    int warpN = (wid & 1) * 64;
    int g = lane >> 2, q = lane & 3;
    int lk4 = tid & 3, lm = tid >> 2;

    float acc[2][8][4];
    #pragma unroll
    for (int mt = 0; mt < 2; mt++)
        #pragma unroll
        for (int nt = 0; nt < 8; nt++)
            #pragma unroll
            for (int i = 0; i < 4; i++) acc[mt][nt][i] = 0.f;

    float4 va[2], vb[2];
    #pragma unroll
    for (int p = 0; p < 2; p++) {
        int m = lm + p * 64;
        va[p] = *(const float4*)&A[(size_t)(bm + m) * K + lk4 * 4];
        vb[p] = *(const float4*)&W[(size_t)(bn + m) * K + lk4 * 4];
    }
    #pragma unroll
    for (int p = 0; p < 2; p++) {
        int m = lm + p * 64;
        As[0][lk4*4+0][m] = va[p].x; As[0][lk4*4+1][m] = va[p].y;
        As[0][lk4*4+2][m] = va[p].z; As[0][lk4*4+3][m] = va[p].w;
        Ws[0][lk4*4+0][m] = vb[p].x; Ws[0][lk4*4+1][m] = vb[p].y;
        Ws[0][lk4*4+2][m] = vb[p].z; Ws[0][lk4*4+3][m] = vb[p].w;
    }
    __syncthreads();

    int buf = 0;
    for (int k0 = 0; k0 < K; k0 += 16) {
        bool has_next = (k0 + 16) < K;
        if (has_next) {
            #pragma unroll
            for (int p = 0; p < 2; p++) {
                int m = lm + p * 64;
                va[p] = *(const float4*)&A[(size_t)(bm + m) * K + k0 + 16 + lk4 * 4];
                vb[p] = *(const float4*)&W[(size_t)(bn + m) * K + k0 + 16 + lk4 * 4];
            }
        }
        #pragma unroll
        for (int ks = 0; ks < 2; ks++) {
            int k8 = ks * 8;
            unsigned ah[2][4], al[2][4], bh[8][2], bl[8][2];
            #pragma unroll
            for (int mt = 0; mt < 2; mt++) {
                int row = warpM + mt * 16 + g;
                split2(As[buf][k8 + q][row],         ah[mt][0], al[mt][0]);
                split2(As[buf][k8 + q][row + 8],     ah[mt][1], al[mt][1]);
                split2(As[buf][k8 + 4 + q][row],     ah[mt][2], al[mt][2]);
                split2(As[buf][k8 + 4 + q][row + 8], ah[mt][3], al[mt][3]);
            }
            #pragma unroll
            for (int nt = 0; nt < 8; nt++) {
                int col = warpN + nt * 8 + g;
                split2(Ws[buf][k8 + q][col],     bh[nt][0], bl[nt][0]);
                split2(Ws[buf][k8 + 4 + q][col], bh[nt][1], bl[nt][1]);
            }
            #pragma unroll
            for (int mt = 0; mt < 2; mt++)
                #pragma unroll
                for (int nt = 0; nt < 8; nt++) {
                    mma_tf32(acc[mt][nt], ah[mt], bh[nt]);
                    mma_tf32(acc[mt][nt], ah[mt], bl[nt]);
                    mma_tf32(acc[mt][nt], al[mt], bh[nt]);
                }
        }
        if (has_next) {
            int nb = buf ^ 1;
            #pragma unroll
            for (int p = 0; p < 2; p++) {
                int m = lm + p * 64;
                As[nb][lk4*4+0][m] = va[p].x; As[nb][lk4*4+1][m] = va[p].y;
                As[nb][lk4*4+2][m] = va[p].z; As[nb][lk4*4+3][m] = va[p].w;
                Ws[nb][lk4*4+0][m] = vb[p].x; Ws[nb][lk4*4+1][m] = vb[p].y;
                Ws[nb][lk4*4+2][m] = vb[p].z; Ws[nb][lk4*4+3][m] = vb[p].w;
            }
            __syncthreads();
            buf = nb;
        }
    }

    #pragma unroll
    for (int mt = 0; mt < 2; mt++) {
        int r0 = bm + warpM + mt * 16 + g;
        #pragma unroll
        for (int nt = 0; nt < 8; nt++) {
            int n = bn + warpN + nt * 8 + q * 2;
            float bia0 = bias[n], bia1 = bias[n + 1];
            float2 vlo = make_float2((acc[mt][nt][0] + bia0) * scale,
                                     (acc[mt][nt][1] + bia1) * scale);
            float2 vhi = make_float2((acc[mt][nt][2] + bia0) * scale,
                                     (acc[mt][nt][3] + bia1) * scale);
            if (REMAP) {
                int h = n >> 6, d = n & 63;
                int b0i = r0 >> 11, s0 = r0 & (SS - 1);
                int b1i = (r0 + 8) >> 11, s1 = (r0 + 8) & (SS - 1);
                *(float2*)&C[(((size_t)b0i * HH + h) * SS + s0) * DD + d] = vlo;
                *(float2*)&C[(((size_t)b1i * HH + h) * SS + s1) * DD + d] = vhi;
            } else {
                *(float2*)&C[(size_t)r0 * EDIM + n] = vlo;
                *(float2*)&C[(size_t)(r0 + 8) * EDIM + n] = vhi;
            }
        }
    }
}

// Fused Q/K/V projection: blockIdx.z selects {W,bias,out,scale}. 768 CTAs = 5.2
// waves on 148 SMs (vs 3 x 1.73-wave launches): one partial tail instead of three.
__global__ __launch_bounds__(256)
void qkv_proj(const float* __restrict__ x,
              const float* __restrict__ Wq, const float* __restrict__ bq,
              const float* __restrict__ Wk, const float* __restrict__ bk,
              const float* __restrict__ Wv, const float* __restrict__ bv,
              float* __restrict__ q, float* __restrict__ k, float* __restrict__ v,
              float qscale)
{
    __shared__ float As[2][16][132];
    __shared__ float Ws[2][16][132];
    int z = blockIdx.z;
    const float* W    = (z == 0) ? Wq : (z == 1) ? Wk : Wv;
    const float* bias = (z == 0) ? bq : (z == 1) ? bk : bv;
    float* C          = (z == 0) ? q  : (z == 1) ? k  : v;
    float scale       = (z == 0) ? qscale : 1.f;
    gemm_body<true>(x, W, bias, C, scale, As, Ws,
                    blockIdx.y * 128, blockIdx.x * 128);
}

// Output projection (single GEMM)
__global__ __launch_bounds__(256)
void out_proj(const float* __restrict__ A, const float* __restrict__ W,
              const float* __restrict__ bias, float* __restrict__ C)
{
    __shared__ float As[2][16][132];
    __shared__ float Ws[2][16][132];
    gemm_body<false>(A, W, bias, C, 1.f, As, Ws,
                     blockIdx.y * 128, blockIdx.x * 128);
}

// ---------------- Tensor-core flash attention ----------------
// CTA: 128 q-rows, key tiles of 64. 8 warps, each 16 q-rows x all 64 keys.
// Q expected pre-scaled by 0.125*log2(e); softmax uses ex2.
// smem (floats): Qs[128][68] @0, Ks[2][64][68] @8704, Vs[2][64][72] @17408.
// All fragment LDS patterns conflict-free (4g+q / 8q+g distinct mod 32).
#define FLASH_SMEM_BYTES 106496

__global__ void __launch_bounds__(256, 2)
flash_attn_tc(const float* __restrict__ Q, const float* __restrict__ K,
              const float* __restrict__ V, float* __restrict__ O)
{
    extern __shared__ char smem_raw[];
    float* smf = (float*)smem_raw;
    unsigned smem_u32 = (unsigned)__cvta_generic_to_shared(smem_raw);

    int tid = threadIdx.x;
    int lane = tid & 31, wid = tid >> 5;
    int g = lane >> 2, qd = lane & 3;
    int warpQ = wid * 16;
    int h = blockIdx.y, b = blockIdx.z;
    const size_t base = ((size_t)b * HH + h) * SS * DD;
    int q0 = blockIdx.x * 128;

    // prologue: cp.async K/V tile 0 -> buf 0
    #pragma unroll
    for (int i = 0; i < 4; i++) {
        int c2 = tid + i * 256;
        int key = c2 >> 4, ch = c2 & 15;
        cp_async16(smem_u32 + (8704 + key * 68 + ch * 4) * 4,
                   &K[base + (size_t)key * DD + ch * 4]);
        cp_async16(smem_u32 + (17408 + key * 72 + ch * 4) * 4,
                   &V[base + (size_t)key * DD + ch * 4]);
    }
    CP_COMMIT();

    // load Q tile [128][64] -> Qs[128][68] (pitch 68 floats = 272B, 16B-aligned)
    #pragma unroll
    for (int i = 0; i < 8; i++) {
        int c2 = tid + i * 256;
        int row = c2 >> 4, ch = c2 & 15;
        float4 v = *(const float4*)&Q[base + (size_t)(q0 + row) * DD + ch * 4];
        *(float4*)&smf[row * 68 + ch * 4] = v;
    }

    float s[8][4], o[8][4];
    #pragma unroll
    for (int t = 0; t < 8; t++)
        #pragma unroll
        for (int j = 0; j < 4; j++) o[t][j] = 0.f;
    float mI0 = -1e30f, mI1 = -1e30f, lI0 = 0.f, lI1 = 0.f;

    const int NKT = SS / 64;
    for (int kt = 0; kt < NKT; kt++) {
        int buf = kt & 1;
        CP_WAIT0();
        __syncthreads();   // tile kt ready; everyone done with buf^1 from kt-1
        if (kt + 1 < NKT) {
            int k0n = (kt + 1) * 64;
            int nb = buf ^ 1;
            #pragma unroll
            for (int i = 0; i < 4; i++) {
                int c2 = tid + i * 256;
                int key = c2 >> 4, ch = c2 & 15;
                cp_async16(smem_u32 + (8704 + nb * 4352 + key * 68 + ch * 4) * 4,
                           &K[base + (size_t)(k0n + key) * DD + ch * 4]);
                cp_async16(smem_u32 + (17408 + nb * 4608 + key * 72 + ch * 4) * 4,
                           &V[base + (size_t)(k0n + key) * DD + ch * 4]);
            }
            CP_COMMIT();
        }
        const float* Kb = smf + 8704 + buf * 4352;
        const float* Vb = smf + 17408 + buf * 4608;

        // ---- S = Q K^T (3xtf32), warp tile 16x64, k over d=64 ----
        #pragma unroll
        for (int t = 0; t < 8; t++) {
            s[t][0] = 0.f; s[t][1] = 0.f; s[t][2] = 0.f; s[t][3] = 0.f;
        }
        #pragma unroll
        for (int k8 = 0; k8 < 8; k8++) {
            unsigned ah[4], al[4];
            split2(smf[(warpQ + g) * 68 + k8 * 8 + qd],         ah[0], al[0]);
            split2(smf[(warpQ + g + 8) * 68 + k8 * 8 + qd],     ah[1], al[1]);
            split2(smf[(warpQ + g) * 68 + k8 * 8 + qd + 4],     ah[2], al[2]);
            split2(smf[(warpQ + g + 8) * 68 + k8 * 8 + qd + 4], ah[3], al[3]);
            #pragma unroll
            for (int t = 0; t < 8; t++) {
                unsigned bh[2], bl[2];
                split2(Kb[(t * 8 + g) * 68 + k8 * 8 + qd],     bh[0], bl[0]);
                split2(Kb[(t * 8 + g) * 68 + k8 * 8 + qd + 4], bh[1], bl[1]);
                mma_tf32(s[t], ah, bh);
                mma_tf32(s[t], ah, bl);
                mma_tf32(s[t], al, bh);
            }
        }

        // ---- online softmax: rows g (s[.][0,1]) and g+8 (s[.][2,3]); quad reduce ----
        float mt0 = -1e30f, mt1 = -1e30f;
        #pragma unroll
        for (int t = 0; t < 8; t++) {
            mt0 = fmaxf(mt0, fmaxf(s[t][0], s[t][1]));
            mt1 = fmaxf(mt1, fmaxf(s[t][2], s[t][3]));
        }
        mt0 = fmaxf(mt0, __shfl_xor_sync(0xffffffffu, mt0, 1));
        mt0 = fmaxf(mt0, __shfl_xor_sync(0xffffffffu, mt0, 2));
        mt1 = fmaxf(mt1, __shfl_xor_sync(0xffffffffu, mt1, 1));
        mt1 = fmaxf(mt1, __shfl_xor_sync(0xffffffffu, mt1, 2));
        float m0 = fmaxf(mI0, mt0), m1 = fmaxf(mI1, mt1);
        float c0 = ex2(mI0 - m0), c1 = ex2(mI1 - m1);
        float rs0 = 0.f, rs1 = 0.f;
        #pragma unroll
        for (int t = 0; t < 8; t++) {
            s[t][0] = ex2(s[t][0] - m0); rs0 += s[t][0];
            s[t][1] = ex2(s[t][1] - m0); rs0 += s[t][1];
            s[t][2] = ex2(s[t][2] - m1); rs1 += s[t][2];
            s[t][3] = ex2(s[t][3] - m1); rs1 += s[t][3];
        }
        rs0 += __shfl_xor_sync(0xffffffffu, rs0, 1);
        rs0 += __shfl_xor_sync(0xffffffffu, rs0, 2);
        rs1 += __shfl_xor_sync(0xffffffffu, rs1, 1);
        rs1 += __shfl_xor_sync(0xffffffffu, rs1, 2);
        lI0 = lI0 * c0 + rs0; mI0 = m0;
        lI1 = lI1 * c1 + rs1; mI1 = m1;
        #pragma unroll
        for (int nd = 0; nd < 8; nd++) {
            o[nd][0] *= c0; o[nd][1] *= c0;
            o[nd][2] *= c1; o[nd][3] *= c1;
        }

        // ---- O += P V : P A-frags built via quad shuffles ----
        #pragma unroll
        for (int t = 0; t < 8; t++) {
            int src = (g << 2) + (qd >> 1);
            float x0 = __shfl_sync(0xffffffffu, s[t][0], src);
            float x1 = __shfl_sync(0xffffffffu, s[t][1], src);
            float x2 = __shfl_sync(0xffffffffu, s[t][2], src);
            float x3 = __shfl_sync(0xffffffffu, s[t][3], src);
            float y0 = __shfl_sync(0xffffffffu, s[t][0], src + 2);
            float y1 = __shfl_sync(0xffffffffu, s[t][1], src + 2);
            float y2 = __shfl_sync(0xffffffffu, s[t][2], src + 2);
            float y3 = __shfl_sync(0xffffffffu, s[t][3], src + 2);
            bool odd = qd & 1;
            unsigned ah[4], al[4];
            split2(odd ? x1 : x0, ah[0], al[0]);
            split2(odd ? x3 : x2, ah[1], al[1]);
            split2(odd ? y1 : y0, ah[2], al[2]);
            split2(odd ? y3 : y2, ah[3], al[3]);
            #pragma unroll
            for (int nd = 0; nd < 8; nd++) {
                unsigned bh[2], bl[2];
                split2(Vb[(t * 8 + qd) * 72 + nd * 8 + g],     bh[0], bl[0]);
                split2(Vb[(t * 8 + qd + 4) * 72 + nd * 8 + g], bh[1], bl[1]);
                mma_tf32(o[nd], ah, bh);
                mma_tf32(o[nd], ah, bl);
                mma_tf32(o[nd], al, bh);
            }
        }
    }

    // ---- normalize and write [N, E] for output projection ----
    float inv0 = 1.f / lI0, inv1 = 1.f / lI1;
    size_t n0 = (size_t)b * SS + q0 + warpQ + g;
    size_t n1 = n0 + 8;
    int col0 = h * 64;
    #pragma unroll
    for (int nd = 0; nd < 8; nd++) {
        *(float2*)&O[n0 * EDIM + col0 + nd * 8 + 2 * qd] =
            make_float2(o[nd][0] * inv0, o[nd][1] * inv0);
        *(float2*)&O[n1 * EDIM + col0 + nd * 8 + 2 * qd] =
            make_float2(o[nd][2] * inv1, o[nd][3] * inv1);
    }
}

extern "C" void kernel_launch(void* const* d_in, const int* in_sizes, int n_in,
                              void* d_out, int out_size) {
    const float* x  = (const float*)d_in[0];
    const float* Wq = (const float*)d_in[1];
    const float* bq = (const float*)d_in[2];
    const float* Wk = (const float*)d_in[3];
    const float* bk = (const float*)d_in[4];
    const float* Wv = (const float*)d_in[5];
    const float* bv = (const float*)d_in[6];
    const float* Wo = (const float*)d_in[7];
    const float* bo = (const float*)d_in[8];
    float* out = (float*)d_out;

    float *q, *k, *v, *attn;
    cudaGetSymbolAddress((void**)&q, g_q);
    cudaGetSymbolAddress((void**)&k, g_k);
    cudaGetSymbolAddress((void**)&v, g_v);
    cudaGetSymbolAddress((void**)&attn, g_attn);

    cudaFuncSetAttribute(flash_attn_tc, cudaFuncAttributeMaxDynamicSharedMemorySize,
                         FLASH_SMEM_BYTES);

    dim3 gthr(256);

    // 1/sqrt(64) * log2(e): softmax computed with ex2
    const float qscale = 0.18033688011112042f;
    qkv_proj<<<dim3(EDIM / 128, NTOK / 128, 3), gthr>>>(
        x, Wq, bq, Wk, bk, Wv, bv, q, k, v, qscale);

    flash_attn_tc<<<dim3(SS / 128, HH, BB), 256, FLASH_SMEM_BYTES>>>(q, k, v, attn);

    out_proj<<<dim3(EDIM / 128, NTOK / 128), gthr>>>(attn, Wo, bo, out);
}